// round 1
// baseline (speedup 1.0000x reference)
#include <cuda_runtime.h>
#include <math.h>

#define BB 16
#define SS 512
#define HH 1024
#define KSLOT 32
#define EE 1024

// ---------------- scratch (no allocations allowed) ----------------
__device__ float g_naf[BB * HH];          // naf projection of cls token
__device__ float g_ch [BB * HH];          // tanh(cls @ cls_dense_W + b)
__device__ float g_fn [BB * KSLOT * HH];  // full_nodes
__device__ float g_Wa [HH * HH];          // W0 + W2 (for nj)
__device__ float g_Wb [HH * HH];          // W1 - W2 (for ni)
__device__ float g_A  [BB * KSLOT * HH];  // full_nodes @ Wa
__device__ float g_Bm [BB * KSLOT * HH];  // full_nodes @ Wb
__device__ float g_Hn [BB * KSLOT * HH];  // tanh(full_nodes @ node_dense_W + b)
__device__ int   g_m  [BB];

// ---------------- helpers ----------------
__device__ __forceinline__ void block_reduce2(float& p0, float& p1, float* sred) {
    int tid = threadIdx.x;
    #pragma unroll
    for (int o = 16; o > 0; o >>= 1) {
        p0 += __shfl_down_sync(0xffffffffu, p0, o);
        p1 += __shfl_down_sync(0xffffffffu, p1, o);
    }
    int w = tid >> 5;
    if ((tid & 31) == 0) { sred[w * 2] = p0; sred[w * 2 + 1] = p1; }
    __syncthreads();
    if (tid < 2) {
        float a = 0.f;
        int nw = blockDim.x >> 5;
        for (int ww = 0; ww < nw; ww++) a += sred[ww * 2 + tid];
        sred[tid] = a;
    }
    __syncthreads();
    p0 = sred[0]; p1 = sred[1];
    __syncthreads();   // smem safe for reuse
}

// ---------------- 1) fold edge weight blocks ----------------
__global__ void prep_w(const float* __restrict__ eW) {
    int idx = blockIdx.x * blockDim.x + threadIdx.x;
    if (idx < HH * HH) {
        float w0 = eW[idx];
        float w1 = eW[HH * HH + idx];
        float w2 = eW[2 * HH * HH + idx];
        g_Wa[idx] = w0 + w2;
        g_Wb[idx] = w1 - w2;
    }
}

// ---------------- 2) cls token: naf + cls hidden ----------------
// grid (B, 4), 256 threads; each thread owns one output column of both mats.
__global__ void cls_kernel(const float* __restrict__ seq,
                           const float* __restrict__ nafW, const float* __restrict__ nafb,
                           const float* __restrict__ cdW,  const float* __restrict__ cdb) {
    __shared__ float s_x[HH];
    int b = blockIdx.x;
    int tid = threadIdx.x;
    int c = blockIdx.y * 256 + tid;
    for (int h = tid; h < HH; h += 256) s_x[h] = seq[(size_t)b * SS * HH + h];
    __syncthreads();
    float an = 0.f, ac = 0.f;
    for (int k = 0; k < HH; k++) {
        float x = s_x[k];
        an = fmaf(x, nafW[(size_t)k * HH + c], an);
        ac = fmaf(x, cdW [(size_t)k * HH + c], ac);
    }
    g_naf[b * HH + c] = an + nafb[c];
    g_ch [b * HH + c] = tanhf(ac + cdb[c]);
}

// ---------------- 3) segment means -> full_nodes ----------------
// grid (B, 32), 128 threads.
__global__ void nodes_kernel(const float* __restrict__ seq, const int* __restrict__ off) {
    int b = blockIdx.x, k = blockIdx.y, tid = threadIdx.x;
    const int* po = off + b * KSLOT;   // po[0]=1, po[1..] = cumsum ends (0 if unused)
    int n = 0;
    #pragma unroll
    for (int t = 1; t < KSLOT; t++) n += (po[t] > 0);
    float* dst = g_fn + ((size_t)(b * KSLOT + k)) * HH;
    if (k < n) {
        int start = (k == 0) ? 1 : po[k] + 1;
        int end   = po[k + 1];
        float inv = 1.0f / (float)(end - start + 1);
        for (int h = tid; h < HH; h += 128) {
            float acc = 0.f;
            for (int r = start; r <= end; r++) acc += seq[((size_t)b * SS + r) * HH + h];
            dst[h] = acc * inv;
        }
    } else if (k == n) {
        for (int h = tid; h < HH; h += 128) dst[h] = g_naf[b * HH + h];
    } else {
        for (int h = tid; h < HH; h += 128) dst[h] = 0.f;
    }
    if (k == 0 && tid == 0) g_m[b] = n + 1;
}

// ---------------- 4) big GEMM: C[512,1024] = g_fn @ W (3 weight mats) ----------------
// 64x64 tile, BK=16, 256 threads, 4x4 microtile.
__global__ void big_gemm(const float* __restrict__ ndW, const float* __restrict__ ndb) {
    const int BM = 64, BN = 64, BK = 16;
    __shared__ float Xs[BK][BM];
    __shared__ float Ws[BK][BN];
    int z = blockIdx.z;
    const float* Wp = (z == 0) ? ndW : (z == 1) ? g_Wa : g_Wb;
    float*       Cp = (z == 0) ? g_Hn : (z == 1) ? g_A : g_Bm;
    int bm = blockIdx.x * BM, bn = blockIdx.y * BN;
    int tid = threadIdx.x;
    int tx = tid & 15, ty = tid >> 4;
    float acc[4][4] = {};
    for (int k0 = 0; k0 < HH; k0 += BK) {
        for (int i = tid; i < BM * BK; i += 256) {
            int r = i >> 4, c = i & 15;
            Xs[c][r] = g_fn[(size_t)(bm + r) * HH + k0 + c];
        }
        for (int i = tid; i < BK * BN; i += 256) {
            int c = i >> 6, nn = i & 63;
            Ws[c][nn] = Wp[(size_t)(k0 + c) * HH + bn + nn];
        }
        __syncthreads();
        #pragma unroll
        for (int kk = 0; kk < BK; kk++) {
            float xr[4], wr[4];
            #pragma unroll
            for (int i = 0; i < 4; i++) xr[i] = Xs[kk][ty * 4 + i];
            #pragma unroll
            for (int j = 0; j < 4; j++) wr[j] = Ws[kk][tx * 4 + j];
            #pragma unroll
            for (int i = 0; i < 4; i++)
                #pragma unroll
                for (int j = 0; j < 4; j++)
                    acc[i][j] = fmaf(xr[i], wr[j], acc[i][j]);
        }
        __syncthreads();
    }
    #pragma unroll
    for (int i = 0; i < 4; i++) {
        int r = bm + ty * 4 + i;
        #pragma unroll
        for (int j = 0; j < 4; j++) {
            int c = bn + tx * 4 + j;
            float v = acc[i][j];
            if (z == 0) v = tanhf(v + ndb[c]);
            Cp[(size_t)r * HH + c] = v;
        }
    }
}

// ---------------- 5) node + cls logits (1024 -> 2 dots) ----------------
// grid 512+16 blocks, 128 threads.
__global__ void logits_kernel(const float* __restrict__ noW, const float* __restrict__ nob,
                              const float* __restrict__ coW, const float* __restrict__ cob,
                              float* __restrict__ out) {
    __shared__ float sred[8];
    int row = blockIdx.x;
    int tid = threadIdx.x;
    const float* src;
    const float* Wv;
    const float* bv;
    float* dst;
    if (row < BB * KSLOT) {
        src = g_Hn + (size_t)row * HH; Wv = noW; bv = nob; dst = out + 32 + row * 2;
    } else {
        int b = row - BB * KSLOT;
        src = g_ch + (size_t)b * HH;  Wv = coW; bv = cob; dst = out + b * 2;
    }
    float p0 = 0.f, p1 = 0.f;
    for (int h = tid; h < HH; h += 128) {
        float v = src[h];
        p0 = fmaf(v, Wv[h * 2],     p0);
        p1 = fmaf(v, Wv[h * 2 + 1], p1);
    }
    block_reduce2(p0, p1, sred);
    if (tid == 0) { dst[0] = p0 + bv[0]; dst[1] = p1 + bv[1]; }
}

// ---------------- 6) edges ----------------
// grid (B, 33), 256 threads. blockIdx.y==i<32: edges e=i*m+j; ==32: invalid tail.
__global__ void edge_kernel(const float* __restrict__ eb,
                            const float* __restrict__ eoW, const float* __restrict__ eob,
                            float* __restrict__ out) {
    __shared__ float s_B[HH];
    __shared__ float s_eb[HH];
    __shared__ float s_w0[HH];
    __shared__ float s_w1[HH];
    __shared__ float sred[16];
    int b = blockIdx.x, i = blockIdx.y, tid = threadIdx.x;
    int m = g_m[b];
    float* outp = out + 32 + BB * KSLOT * 2;   // edge logits start at 1056
    for (int h = tid; h < HH; h += 256) {
        s_eb[h] = eb[h];
        s_w0[h] = eoW[h * 2];
        s_w1[h] = eoW[h * 2 + 1];
    }
    if (i < KSLOT) {
        if (i >= m) return;
        for (int h = tid; h < HH; h += 256)
            s_B[h] = g_Bm[((size_t)(b * KSLOT + i)) * HH + h];
        __syncthreads();
        for (int j = 0; j < m; j++) {
            const float* Aj = g_A + ((size_t)(b * KSLOT + j)) * HH;
            float p0 = 0.f, p1 = 0.f;
            for (int h = tid; h < HH; h += 256) {
                float v = tanhf(Aj[h] + s_B[h] + s_eb[h]);
                p0 = fmaf(v, s_w0[h], p0);
                p1 = fmaf(v, s_w1[h], p1);
            }
            block_reduce2(p0, p1, sred);
            if (tid == 0) {
                int e = i * m + j;
                outp[((size_t)b * EE + e) * 2]     = p0 + eob[0];
                outp[((size_t)b * EE + e) * 2 + 1] = p1 + eob[1];
            }
        }
    } else {
        __syncthreads();
        float p0 = 0.f, p1 = 0.f;
        for (int h = tid; h < HH; h += 256) {
            float v = tanhf(s_eb[h]);
            p0 = fmaf(v, s_w0[h], p0);
            p1 = fmaf(v, s_w1[h], p1);
        }
        block_reduce2(p0, p1, sred);
        float c0 = p0 + eob[0], c1 = p1 + eob[1];
        for (int e = m * m + tid; e < EE; e += 256) {
            outp[((size_t)b * EE + e) * 2]     = c0;
            outp[((size_t)b * EE + e) * 2 + 1] = c1;
        }
    }
}

// ---------------- launch ----------------
extern "C" void kernel_launch(void* const* d_in, const int* in_sizes, int n_in,
                              void* d_out, int out_size) {
    const float* seq  = (const float*)d_in[0];
    const int*   off  = (const int*)  d_in[1];
    const float* nafW = (const float*)d_in[2];
    const float* nafb = (const float*)d_in[3];
    const float* cdW  = (const float*)d_in[4];
    const float* cdb  = (const float*)d_in[5];
    const float* coW  = (const float*)d_in[6];
    const float* cob  = (const float*)d_in[7];
    const float* ndW  = (const float*)d_in[8];
    const float* ndb  = (const float*)d_in[9];
    const float* noW  = (const float*)d_in[10];
    const float* nob  = (const float*)d_in[11];
    const float* edW  = (const float*)d_in[12];
    const float* edb  = (const float*)d_in[13];
    const float* eoW  = (const float*)d_in[14];
    const float* eob  = (const float*)d_in[15];
    float* out = (float*)d_out;

    prep_w<<<(HH * HH + 255) / 256, 256>>>(edW);
    cls_kernel<<<dim3(BB, 4), 256>>>(seq, nafW, nafb, cdW, cdb);
    nodes_kernel<<<dim3(BB, KSLOT), 128>>>(seq, off);
    big_gemm<<<dim3(512 / 64, HH / 64, 3), 256>>>(ndW, ndb);
    logits_kernel<<<BB * KSLOT + BB, 128>>>(noW, nob, coW, cob, out);
    edge_kernel<<<dim3(BB, KSLOT + 1), 256>>>(edb, eoW, eob, out);
}

// round 2
// speedup vs baseline: 1.1241x; 1.1241x over previous
#include <cuda_runtime.h>
#include <math.h>

#define BB 16
#define SS 512
#define HH 1024
#define KSLOT 32
#define EE 1024

// ---------------- scratch (no allocations allowed) ----------------
__device__ float g_naf[BB * HH];          // naf projection of cls token
__device__ float g_ch [BB * HH];          // tanh(cls @ cls_dense_W + b)
__device__ float g_fn [BB * KSLOT * HH];  // full_nodes
__device__ float g_Wa [HH * HH];          // W0 + W2 (for nj)
__device__ float g_Wb [HH * HH];          // W1 - W2 (for ni)
__device__ float g_A  [BB * KSLOT * HH];  // full_nodes @ Wa
__device__ float g_Bm [BB * KSLOT * HH];  // full_nodes @ Wb
__device__ float g_Hn [BB * KSLOT * HH];  // tanh(full_nodes @ node_dense_W + b)
__device__ int   g_m  [BB];

// ---------------- helpers ----------------
__device__ __forceinline__ void block_reduce2(float& p0, float& p1, float* sred) {
    int tid = threadIdx.x;
    #pragma unroll
    for (int o = 16; o > 0; o >>= 1) {
        p0 += __shfl_down_sync(0xffffffffu, p0, o);
        p1 += __shfl_down_sync(0xffffffffu, p1, o);
    }
    int w = tid >> 5;
    if ((tid & 31) == 0) { sred[w * 2] = p0; sred[w * 2 + 1] = p1; }
    __syncthreads();
    if (tid < 2) {
        float a = 0.f;
        int nw = blockDim.x >> 5;
        for (int ww = 0; ww < nw; ww++) a += sred[ww * 2 + tid];
        sred[tid] = a;
    }
    __syncthreads();
    p0 = sred[0]; p1 = sred[1];
    __syncthreads();   // smem safe for reuse
}

// ---------------- 1) fold edge weight blocks ----------------
__global__ void prep_w(const float* __restrict__ eW) {
    int idx = blockIdx.x * blockDim.x + threadIdx.x;
    if (idx < HH * HH) {
        float w0 = eW[idx];
        float w1 = eW[HH * HH + idx];
        float w2 = eW[2 * HH * HH + idx];
        g_Wa[idx] = w0 + w2;
        g_Wb[idx] = w1 - w2;
    }
}

// ---------------- 2) cls token: naf + cls hidden ----------------
__global__ void cls_kernel(const float* __restrict__ seq,
                           const float* __restrict__ nafW, const float* __restrict__ nafb,
                           const float* __restrict__ cdW,  const float* __restrict__ cdb) {
    __shared__ float s_x[HH];
    int b = blockIdx.x;
    int tid = threadIdx.x;
    int c = blockIdx.y * 256 + tid;
    for (int h = tid; h < HH; h += 256) s_x[h] = seq[(size_t)b * SS * HH + h];
    __syncthreads();
    float an = 0.f, ac = 0.f;
    for (int k = 0; k < HH; k++) {
        float x = s_x[k];
        an = fmaf(x, nafW[(size_t)k * HH + c], an);
        ac = fmaf(x, cdW [(size_t)k * HH + c], ac);
    }
    g_naf[b * HH + c] = an + nafb[c];
    g_ch [b * HH + c] = tanhf(ac + cdb[c]);
}

// ---------------- 3) segment means -> full_nodes ----------------
__global__ void nodes_kernel(const float* __restrict__ seq, const int* __restrict__ off) {
    int b = blockIdx.x, k = blockIdx.y, tid = threadIdx.x;
    const int* po = off + b * KSLOT;
    int n = 0;
    #pragma unroll
    for (int t = 1; t < KSLOT; t++) n += (po[t] > 0);
    float* dst = g_fn + ((size_t)(b * KSLOT + k)) * HH;
    if (k < n) {
        int start = (k == 0) ? 1 : po[k] + 1;
        int end   = po[k + 1];
        float inv = 1.0f / (float)(end - start + 1);
        for (int h = tid; h < HH; h += 128) {
            float acc = 0.f;
            for (int r = start; r <= end; r++) acc += seq[((size_t)b * SS + r) * HH + h];
            dst[h] = acc * inv;
        }
    } else if (k == n) {
        for (int h = tid; h < HH; h += 128) dst[h] = g_naf[b * HH + h];
    } else {
        for (int h = tid; h < HH; h += 128) dst[h] = 0.f;
    }
    if (k == 0 && tid == 0) g_m[b] = n + 1;
}

// ---------------- 4) big GEMM: C[512,1024] = g_fn @ W (3 weight mats) ----------
// 64x64 tile, BK=16, 128 threads, 4x8 microtile, double-buffered, vectorized.
__global__ __launch_bounds__(128) void big_gemm(const float* __restrict__ ndW,
                                                const float* __restrict__ ndb) {
    const int BM = 64, BN = 64, BK = 16;
    const int XPAD = BM + 4;                 // keep 16B align, break bank-conflict stride
    __shared__ float Xs[2][BK][XPAD];
    __shared__ float Ws[2][BK][BN];

    int z = blockIdx.z;
    const float* Wp = (z == 0) ? ndW : (z == 1) ? g_Wa : g_Wb;
    float*       Cp = (z == 0) ? g_Hn : (z == 1) ? g_A : g_Bm;
    int bm = blockIdx.x * BM, bn = blockIdx.y * BN;
    int tid = threadIdx.x;                   // 128
    int tx = tid & 7;                        // 8 col-groups of 8
    int ty = tid >> 3;                       // 16 row-groups of 4

    // --- loader indexing ---
    // X tile (BM rows x BK k): 256 float4 chunks (row, kq<4) -> 2 per thread
    int xc0 = tid * 2;
    int xrow0 = xc0 >> 2,       xkq0 = xc0 & 3;
    int xrow1 = (xc0 + 1) >> 2, xkq1 = (xc0 + 1) & 3;
    // W tile (BK rows x BN cols): 256 float4 chunks (wk, nq<16) -> 2 per thread
    int wc0 = tid * 2;
    int wk0 = wc0 >> 4,       wnq0 = wc0 & 15;
    int wk1 = (wc0 + 1) >> 4, wnq1 = (wc0 + 1) & 15;

    const float4* Xg = (const float4*)(g_fn);
    const float4* Wg = (const float4*)(Wp);
    // float4 index helpers: row-major HH floats per row -> HH/4 float4 per row
    const int H4 = HH / 4;

    float4 xa, xb, wa, wb;
    // prefetch tile 0
    {
        int k0 = 0;
        xa = Xg[(size_t)(bm + xrow0) * H4 + (k0 >> 2) + xkq0];
        xb = Xg[(size_t)(bm + xrow1) * H4 + (k0 >> 2) + xkq1];
        wa = Wg[(size_t)(k0 + wk0) * H4 + (bn >> 2) + wnq0];
        wb = Wg[(size_t)(k0 + wk1) * H4 + (bn >> 2) + wnq1];
    }
    // store tile 0
    {
        Xs[0][xkq0 * 4 + 0][xrow0] = xa.x; Xs[0][xkq0 * 4 + 1][xrow0] = xa.y;
        Xs[0][xkq0 * 4 + 2][xrow0] = xa.z; Xs[0][xkq0 * 4 + 3][xrow0] = xa.w;
        Xs[0][xkq1 * 4 + 0][xrow1] = xb.x; Xs[0][xkq1 * 4 + 1][xrow1] = xb.y;
        Xs[0][xkq1 * 4 + 2][xrow1] = xb.z; Xs[0][xkq1 * 4 + 3][xrow1] = xb.w;
        *(float4*)&Ws[0][wk0][wnq0 * 4] = wa;
        *(float4*)&Ws[0][wk1][wnq1 * 4] = wb;
    }
    __syncthreads();

    float acc[4][8];
    #pragma unroll
    for (int i = 0; i < 4; i++)
        #pragma unroll
        for (int j = 0; j < 8; j++) acc[i][j] = 0.f;

    int buf = 0;
    const int NT = HH / BK;                  // 64 k-tiles
    for (int kt = 0; kt < NT; kt++) {
        if (kt + 1 < NT) {
            int k0 = (kt + 1) * BK;
            xa = Xg[(size_t)(bm + xrow0) * H4 + (k0 >> 2) + xkq0];
            xb = Xg[(size_t)(bm + xrow1) * H4 + (k0 >> 2) + xkq1];
            wa = Wg[(size_t)(k0 + wk0) * H4 + (bn >> 2) + wnq0];
            wb = Wg[(size_t)(k0 + wk1) * H4 + (bn >> 2) + wnq1];
        }
        #pragma unroll
        for (int kk = 0; kk < BK; kk++) {
            float4 xv  = *(const float4*)&Xs[buf][kk][ty * 4];
            float4 wv0 = *(const float4*)&Ws[buf][kk][tx * 8];
            float4 wv1 = *(const float4*)&Ws[buf][kk][tx * 8 + 4];
            float xr[4] = {xv.x, xv.y, xv.z, xv.w};
            float wr[8] = {wv0.x, wv0.y, wv0.z, wv0.w, wv1.x, wv1.y, wv1.z, wv1.w};
            #pragma unroll
            for (int i = 0; i < 4; i++)
                #pragma unroll
                for (int j = 0; j < 8; j++)
                    acc[i][j] = fmaf(xr[i], wr[j], acc[i][j]);
        }
        if (kt + 1 < NT) {
            int nb = buf ^ 1;
            Xs[nb][xkq0 * 4 + 0][xrow0] = xa.x; Xs[nb][xkq0 * 4 + 1][xrow0] = xa.y;
            Xs[nb][xkq0 * 4 + 2][xrow0] = xa.z; Xs[nb][xkq0 * 4 + 3][xrow0] = xa.w;
            Xs[nb][xkq1 * 4 + 0][xrow1] = xb.x; Xs[nb][xkq1 * 4 + 1][xrow1] = xb.y;
            Xs[nb][xkq1 * 4 + 2][xrow1] = xb.z; Xs[nb][xkq1 * 4 + 3][xrow1] = xb.w;
            *(float4*)&Ws[nb][wk0][wnq0 * 4] = wa;
            *(float4*)&Ws[nb][wk1][wnq1 * 4] = wb;
            __syncthreads();
            buf = nb;
        }
    }

    // epilogue
    float bias[8];
    if (z == 0) {
        #pragma unroll
        for (int j = 0; j < 8; j++) bias[j] = ndb[bn + tx * 8 + j];
    }
    #pragma unroll
    for (int i = 0; i < 4; i++) {
        int r = bm + ty * 4 + i;
        float* cr = Cp + (size_t)r * HH + bn + tx * 8;
        float4 o0, o1;
        if (z == 0) {
            o0.x = tanhf(acc[i][0] + bias[0]); o0.y = tanhf(acc[i][1] + bias[1]);
            o0.z = tanhf(acc[i][2] + bias[2]); o0.w = tanhf(acc[i][3] + bias[3]);
            o1.x = tanhf(acc[i][4] + bias[4]); o1.y = tanhf(acc[i][5] + bias[5]);
            o1.z = tanhf(acc[i][6] + bias[6]); o1.w = tanhf(acc[i][7] + bias[7]);
        } else {
            o0 = make_float4(acc[i][0], acc[i][1], acc[i][2], acc[i][3]);
            o1 = make_float4(acc[i][4], acc[i][5], acc[i][6], acc[i][7]);
        }
        *(float4*)(cr)     = o0;
        *(float4*)(cr + 4) = o1;
    }
}

// ---------------- 5) node + cls logits (1024 -> 2 dots) ----------------
__global__ void logits_kernel(const float* __restrict__ noW, const float* __restrict__ nob,
                              const float* __restrict__ coW, const float* __restrict__ cob,
                              float* __restrict__ out) {
    __shared__ float sred[8];
    int row = blockIdx.x;
    int tid = threadIdx.x;
    const float* src;
    const float* Wv;
    const float* bv;
    float* dst;
    if (row < BB * KSLOT) {
        src = g_Hn + (size_t)row * HH; Wv = noW; bv = nob; dst = out + 32 + row * 2;
    } else {
        int b = row - BB * KSLOT;
        src = g_ch + (size_t)b * HH;  Wv = coW; bv = cob; dst = out + b * 2;
    }
    float p0 = 0.f, p1 = 0.f;
    for (int h = tid; h < HH; h += 128) {
        float v = src[h];
        p0 = fmaf(v, Wv[h * 2],     p0);
        p1 = fmaf(v, Wv[h * 2 + 1], p1);
    }
    block_reduce2(p0, p1, sred);
    if (tid == 0) { dst[0] = p0 + bv[0]; dst[1] = p1 + bv[1]; }
}

// ---------------- 6) edges ----------------
__global__ void edge_kernel(const float* __restrict__ eb,
                            const float* __restrict__ eoW, const float* __restrict__ eob,
                            float* __restrict__ out) {
    __shared__ float s_B[HH];
    __shared__ float s_eb[HH];
    __shared__ float s_w0[HH];
    __shared__ float s_w1[HH];
    __shared__ float sred[16];
    int b = blockIdx.x, i = blockIdx.y, tid = threadIdx.x;
    int m = g_m[b];
    float* outp = out + 32 + BB * KSLOT * 2;   // edge logits start at 1056
    for (int h = tid; h < HH; h += 256) {
        s_eb[h] = eb[h];
        s_w0[h] = eoW[h * 2];
        s_w1[h] = eoW[h * 2 + 1];
    }
    if (i < KSLOT) {
        if (i >= m) return;
        for (int h = tid; h < HH; h += 256)
            s_B[h] = g_Bm[((size_t)(b * KSLOT + i)) * HH + h];
        __syncthreads();
        for (int j = 0; j < m; j++) {
            const float* Aj = g_A + ((size_t)(b * KSLOT + j)) * HH;
            float p0 = 0.f, p1 = 0.f;
            for (int h = tid; h < HH; h += 256) {
                float v = tanhf(Aj[h] + s_B[h] + s_eb[h]);
                p0 = fmaf(v, s_w0[h], p0);
                p1 = fmaf(v, s_w1[h], p1);
            }
            block_reduce2(p0, p1, sred);
            if (tid == 0) {
                int e = i * m + j;
                outp[((size_t)b * EE + e) * 2]     = p0 + eob[0];
                outp[((size_t)b * EE + e) * 2 + 1] = p1 + eob[1];
            }
        }
    } else {
        __syncthreads();
        float p0 = 0.f, p1 = 0.f;
        for (int h = tid; h < HH; h += 256) {
            float v = tanhf(s_eb[h]);
            p0 = fmaf(v, s_w0[h], p0);
            p1 = fmaf(v, s_w1[h], p1);
        }
        block_reduce2(p0, p1, sred);
        float c0 = p0 + eob[0], c1 = p1 + eob[1];
        for (int e = m * m + tid; e < EE; e += 256) {
            outp[((size_t)b * EE + e) * 2]     = c0;
            outp[((size_t)b * EE + e) * 2 + 1] = c1;
        }
    }
}

// ---------------- launch ----------------
extern "C" void kernel_launch(void* const* d_in, const int* in_sizes, int n_in,
                              void* d_out, int out_size) {
    const float* seq  = (const float*)d_in[0];
    const int*   off  = (const int*)  d_in[1];
    const float* nafW = (const float*)d_in[2];
    const float* nafb = (const float*)d_in[3];
    const float* cdW  = (const float*)d_in[4];
    const float* cdb  = (const float*)d_in[5];
    const float* coW  = (const float*)d_in[6];
    const float* cob  = (const float*)d_in[7];
    const float* ndW  = (const float*)d_in[8];
    const float* ndb  = (const float*)d_in[9];
    const float* noW  = (const float*)d_in[10];
    const float* nob  = (const float*)d_in[11];
    const float* edW  = (const float*)d_in[12];
    const float* edb  = (const float*)d_in[13];
    const float* eoW  = (const float*)d_in[14];
    const float* eob  = (const float*)d_in[15];
    float* out = (float*)d_out;

    prep_w<<<(HH * HH + 255) / 256, 256>>>(edW);
    cls_kernel<<<dim3(BB, 4), 256>>>(seq, nafW, nafb, cdW, cdb);
    nodes_kernel<<<dim3(BB, KSLOT), 128>>>(seq, off);
    big_gemm<<<dim3(512 / 64, HH / 64, 3), 128>>>(ndW, ndb);
    logits_kernel<<<BB * KSLOT + BB, 128>>>(noW, nob, coW, cob, out);
    edge_kernel<<<dim3(BB, KSLOT + 1), 256>>>(edb, eoW, eob, out);
}